// round 11
// baseline (speedup 1.0000x reference)
#include <cuda_runtime.h>
#include <cuda_bf16.h>
#include <cstdint>

typedef unsigned long long u64;

#define ND 2048
#define NB 8192
#define NSQ (ND*ND)

// tcgen05 is arch-SPECIFIC (sm_103a pass only); base compute_103 pass gets a
// SIMT fallback body so ptxas never sees tcgen05 on the base target.
#if defined(__CUDA_ARCH__) && (defined(__CUDA_ARCH_FEAT_SM103_ALL) || defined(__CUDA_ARCH_FEAT_SM100_ALL) || defined(__CUDA_ARCH_FEAT_SM101_ALL))
#define HAS_TCGEN05 1
#else
#define HAS_TCGEN05 0
#endif

// ---------------- scratch (__device__ globals; allocation-free rule) --------
__device__ float g_S [NSQ];
__device__ float g_S2[NSQ];
__device__ float g_S3[NSQ];
__device__ float g_T [NSQ];
__device__ float g_F [NSQ];
__device__ float g_Wf[NSQ];

__device__ __nv_bfloat16 g_sA_hi[NSQ],  g_sA_lo[NSQ];    // S   (A-side)
__device__ __nv_bfloat16 g_sB_hi[NSQ],  g_sB_lo[NSQ];    // S^T = -S (B-side)
__device__ __nv_bfloat16 g_s2_hi[NSQ],  g_s2_lo[NSQ];    // S2  (A-side)
__device__ __nv_bfloat16 g_s3_hi[NSQ],  g_s3_lo[NSQ];    // S3  (A-side)
__device__ __nv_bfloat16 g_w2t_hi[NSQ], g_w2t_lo[NSQ];   // W2^T (B-side)
__device__ __nv_bfloat16 g_f_hi[NSQ],   g_f_lo[NSQ];     // F   (A-side)
__device__ __nv_bfloat16 g_ft_hi[NSQ],  g_ft_lo[NSQ];    // F^T (B-side)
__device__ __nv_bfloat16 g_wft_hi[NSQ], g_wft_lo[NSQ];   // (Wf+I)^T (B-side)
__device__ __nv_bfloat16 g_x_hi[NB*ND], g_x_lo[NB*ND];   // X   (A-side)

// ---------------- common helpers --------------------------------------------
__device__ __forceinline__ void split2(float v, __nv_bfloat16& h, __nv_bfloat16& l) {
    h = __float2bfloat16(v);
    l = __float2bfloat16(v - __bfloat162float(h));
}

#define SWZ128(x) ((x) ^ (((x) >> 3) & 0x70))

#if HAS_TCGEN05
__device__ __forceinline__ uint32_t smem_to_u32(const void* p) {
    uint32_t a;
    asm("{ .reg .u64 t; cvta.to.shared.u64 t, %1; cvt.u32.u64 %0, t; }" : "=r"(a) : "l"(p));
    return a;
}
__device__ __forceinline__ uint32_t elect_one_pred() {
    uint32_t p;
    asm volatile("{\n\t.reg .pred p;\n\telect.sync _|p, 0xFFFFFFFF;\n\t"
                 "selp.b32 %0, 1, 0, p;\n\t}" : "=r"(p));
    return p;
}
#define MBARRIER_INIT(addr, cnt) \
    asm volatile("mbarrier.init.shared.b64 [%0], %1;" :: "r"((uint32_t)(addr)), "r"((uint32_t)(cnt)) : "memory")
#define MBARRIER_INVAL(addr) \
    asm volatile("mbarrier.inval.shared.b64 [%0];" :: "r"((uint32_t)(addr)) : "memory")
#define MBARRIER_WAIT_PARITY(mbar, par) do {                                       \
    uint32_t _m = (uint32_t)(mbar); uint32_t _p = (uint32_t)(par); uint32_t _d;    \
    asm volatile("{\n\t.reg .pred p;\n\t"                                          \
        "mbarrier.try_wait.parity.acquire.cta.shared::cta.b64 p, [%1], %2;\n\t"    \
        "selp.b32 %0, 1, 0, p;\n\t}" : "=r"(_d) : "r"(_m), "r"(_p) : "memory");    \
    if (!_d) {                                                                     \
        asm volatile("{\n\t.reg .pred P1;\n\t"                                     \
        "WL_%=:\n\t"                                                               \
        "mbarrier.try_wait.parity.acquire.cta.shared::cta.b64 P1, [%0], %1, 0x989680;\n\t" \
        "@P1 bra.uni WD_%=;\n\t"                                                   \
        "bra.uni WL_%=;\n\t"                                                       \
        "WD_%=:\n\t}" :: "r"(_m), "r"(_p) : "memory");                             \
    }                                                                              \
} while (0)
// arrive on the same-offset mbarrier in cluster rank 0 (leader)
#define MBAR_ARRIVE_LEADER(localaddr) \
    asm volatile("{\n\t.reg .b32 ra;\n\t" \
        "mapa.shared::cluster.u32 ra, %0, 0;\n\t" \
        "mbarrier.arrive.shared::cluster.b64 _, [ra];\n\t}" \
        :: "r"((uint32_t)(localaddr)) : "memory")
#define CLUSTER_SYNC() do { \
    asm volatile("barrier.cluster.arrive.aligned;" ::: "memory"); \
    asm volatile("barrier.cluster.wait.aligned;" ::: "memory"); \
} while (0)
#define TCGEN05_ALLOC_CG2(sm, n) \
    asm volatile("tcgen05.alloc.cta_group::2.sync.aligned.shared::cta.b32 [%0], %1;" \
                 :: "r"((uint32_t)(sm)), "r"((uint32_t)(n)) : "memory")
#define TCGEN05_DEALLOC_CG2(t, n) \
    asm volatile("tcgen05.dealloc.cta_group::2.sync.aligned.b32 %0, %1;" :: "r"(t), "r"((uint32_t)(n)))
#define TCGEN05_RELINQ_CG2() \
    asm volatile("tcgen05.relinquish_alloc_permit.cta_group::2.sync.aligned;")
#define TCGEN05_COMMIT_MC_CG2(mbar, mask) \
    asm volatile("tcgen05.commit.cta_group::2.mbarrier::arrive::one.shared::cluster.multicast::cluster.b64 [%0], %1;" \
                 :: "r"((uint32_t)(mbar)), "h"((uint16_t)(mask)) : "memory")
#define TCGEN05_FENCE_AFTER()  asm volatile("tcgen05.fence::after_thread_sync;" ::: "memory")
#define TCGEN05_FENCE_BEFORE() asm volatile("tcgen05.fence::before_thread_sync;" ::: "memory")
#define TCGEN05_WAIT_LD()      asm volatile("tcgen05.wait::ld.sync.aligned;" ::: "memory")
#define FENCE_PROXY_ASYNC()    asm volatile("fence.proxy.async;" ::: "memory")
#define CP_ASYNC16(dst, src) \
    asm volatile("cp.async.cg.shared.global [%0], [%1], 16;" :: "r"((uint32_t)(dst)), "l"(src) : "memory")
// arrive-on-completion WITHOUT incrementing the pending count (.noinc):
// the barrier's init count pre-arms one arrive per producer thread. The
// default (non-noinc) form increments-then-arrives (net zero) and would
// never flip a count=256 barrier -> R10 deadlock.
#define CP_ASYNC_MBAR_ARRIVE_NOINC(m) \
    asm volatile("cp.async.mbarrier.arrive.noinc.shared::cta.b64 [%0];" :: "r"((uint32_t)(m)) : "memory")

#define TCGEN05_LD_X32(r, addr) \
    asm volatile("tcgen05.ld.sync.aligned.32x32b.x32.b32 " \
        "{%0, %1, %2, %3, %4, %5, %6, %7, %8, %9, %10, %11, %12, %13, %14, %15, " \
        " %16, %17, %18, %19, %20, %21, %22, %23, %24, %25, %26, %27, %28, %29, %30, %31}, [%32];" \
        : "=r"((r)[0]),  "=r"((r)[1]),  "=r"((r)[2]),  "=r"((r)[3]),  \
          "=r"((r)[4]),  "=r"((r)[5]),  "=r"((r)[6]),  "=r"((r)[7]),  \
          "=r"((r)[8]),  "=r"((r)[9]),  "=r"((r)[10]), "=r"((r)[11]), \
          "=r"((r)[12]), "=r"((r)[13]), "=r"((r)[14]), "=r"((r)[15]), \
          "=r"((r)[16]), "=r"((r)[17]), "=r"((r)[18]), "=r"((r)[19]), \
          "=r"((r)[20]), "=r"((r)[21]), "=r"((r)[22]), "=r"((r)[23]), \
          "=r"((r)[24]), "=r"((r)[25]), "=r"((r)[26]), "=r"((r)[27]), \
          "=r"((r)[28]), "=r"((r)[29]), "=r"((r)[30]), "=r"((r)[31]) \
        : "r"(addr))

// SW128 K-major smem descriptor (layout=2, version=1, SBO=64, LBO=1)
static constexpr u64 DESC_BASE_SW128 =
    (u64(2) << 61) | (u64(1) << 46) | (u64(64) << 32) | (u64(1) << 16);
#define MAKE_DESC(a) (DESC_BASE_SW128 | ((u64)((a) >> 4) & 0x3FFF))

// cg2 bf16 SS MMA: idesc = F32 | BF16 a | BF16 b | (N/8)<<17 | (M/16)<<24
#define MMA_IDESC_CG2 0x10400490u   // M=256 (pair), N=256
__device__ __forceinline__ void mma_f16_ss_cg2(uint32_t d, u64 a, u64 b, uint32_t en) {
    asm volatile("{\n\t.reg .pred p;\n\tsetp.ne.u32 p, %4, 0;\n\t"
        "tcgen05.mma.cta_group::2.kind::f16 [%0], %1, %2, %3, "
        "{%5, %5, %5, %5, %5, %5, %5, %5}, p;\n\t}"
        :: "r"(d), "l"(a), "l"(b), "r"(MMA_IDESC_CG2), "r"(en), "r"(0u) : "memory");
}
#endif  // HAS_TCGEN05

// ---------------- elementwise kernels ---------------------------------------
__global__ void build_S_kernel(float* __restrict__ S, const float* __restrict__ Sf,
                               __nv_bfloat16* __restrict__ ahi, __nv_bfloat16* __restrict__ alo,
                               __nv_bfloat16* __restrict__ bhi, __nv_bfloat16* __restrict__ blo) {
    int idx = blockIdx.x * blockDim.x + threadIdx.x;
    int r = idx >> 11, c = idx & (ND - 1);
    float v = 0.f;
    if (r != c) {
        int rr = r < c ? r : c, cc = r < c ? c : r;
        int f = rr * (2 * ND - rr - 1) / 2 + (cc - rr - 1);
        v = Sf[f];
        if (r > c) v = -v;
    }
    S[idx] = v;
    __nv_bfloat16 h, l;
    split2(v, h, l);  ahi[idx] = h; alo[idx] = l;
    split2(-v, h, l); bhi[idx] = h; blo[idx] = l;   // S^T = -S
}

// W2^T = I/48 - S/384 + S2/3840 - S3/46080 (bf16 split);  T = S2/8 + S/2 (fp32)
__global__ void ew_prep_kernel(__nv_bfloat16* __restrict__ w2hi, __nv_bfloat16* __restrict__ w2lo,
                               float* __restrict__ T,
                               const float* __restrict__ S, const float* __restrict__ S2,
                               const float* __restrict__ S3) {
    int idx = blockIdx.x * blockDim.x + threadIdx.x;
    int r = idx >> 11, c = idx & (ND - 1);
    float s = S[idx], s2 = S2[idx], s3 = S3[idx];
    float w2t = -s3 * (1.f / 46080.f) + s2 * (1.f / 3840.f) - s * (1.f / 384.f);
    if (r == c) w2t += (1.f / 48.f);
    __nv_bfloat16 h, l;
    split2(w2t, h, l); w2hi[idx] = h; w2lo[idx] = l;
    T[idx] = s2 * 0.125f + s * 0.5f;
}

// 32x32 tiled transpose + optional diagonal add + bf16 split
__global__ void transpose_conv(const float* __restrict__ in,
                               __nv_bfloat16* __restrict__ thi, __nv_bfloat16* __restrict__ tlo,
                               float idadd) {
    __shared__ float tile[32][33];
    int bx = blockIdx.x * 32, by = blockIdx.y * 32;
    int tx = threadIdx.x, ty = threadIdx.y;   // 32 x 8
#pragma unroll
    for (int j = 0; j < 4; j++)
        tile[ty + 8 * j][tx] = in[(size_t)(by + ty + 8 * j) * ND + bx + tx];
    __syncthreads();
#pragma unroll
    for (int j = 0; j < 4; j++) {
        int ro = bx + ty + 8 * j, co = by + tx;
        float v = tile[tx][ty + 8 * j];
        if (ro == co) v += idadd;
        __nv_bfloat16 h, l; split2(v, h, l);
        size_t o = (size_t)ro * ND + co;
        thi[o] = h; tlo[o] = l;
    }
}

// row-major fp32 -> hi/lo bf16 (for X)
__global__ void conv_rm(const float* __restrict__ in,
                        __nv_bfloat16* __restrict__ hi, __nv_bfloat16* __restrict__ lo) {
    int i = blockIdx.x * blockDim.x + threadIdx.x;
    float4 v = ((const float4*)in)[i];
    __nv_bfloat16 h0, l0, h1, l1, h2, l2, h3, l3;
    split2(v.x, h0, l0); split2(v.y, h1, l1); split2(v.z, h2, l2); split2(v.w, h3, l3);
    ((__nv_bfloat162*)hi)[2 * i]     = __nv_bfloat162(h0, h1);
    ((__nv_bfloat162*)hi)[2 * i + 1] = __nv_bfloat162(h2, h3);
    ((__nv_bfloat162*)lo)[2 * i]     = __nv_bfloat162(l0, l1);
    ((__nv_bfloat162*)lo)[2 * i + 1] = __nv_bfloat162(l2, l3);
}

// ---------------- GEMM: C = A @ B^T, 2-CTA cluster computes 256x256 tile ----
// TRUE async pipeline: producers issue cp.async + .noinc arrive-on-completion
// onto full_loc[buf] (count=256) and never block on data. Warp0 = consumer
// chain: wait full_loc -> arrive leader full[buf] (count=2) -> rank0 waits
// full -> fence.proxy.async -> 12 cg2 MMAs -> multicast commit -> done[buf].
// Producers gate only on done[buf] (buffer free): loads t+1/t+2 overlap MMA(t).
#define BM 128          // per-CTA M share (pair = 256)
#define BN 256
#define BKB 64
#define SUB 16384                         // one 128x64 bf16 sub-tile
#define STAGE_BY (4 * SUB)                // Ahi,Alo,Bhi,Blo = 64 KB
#define NSTG 3
#define SM_HDR 1024
#define GEMM_SMEM (SM_HDR + NSTG * STAGE_BY)  // 197632 bytes

__global__ void __launch_bounds__(256, 1) __cluster_dims__(2, 1, 1)
gemm_bf3(float* __restrict__ C,
         const __nv_bfloat16* __restrict__ Ahi, const __nv_bfloat16* __restrict__ Alo,
         const __nv_bfloat16* __restrict__ Bhi, const __nv_bfloat16* __restrict__ Blo,
         const float* __restrict__ D, float beta,
         __nv_bfloat16* __restrict__ Chi, __nv_bfloat16* __restrict__ Clo,
         int M, int Nn, int K) {
    extern __shared__ char smem[];
    const int tid = threadIdx.x, wid = tid >> 5, lid = tid & 31;
    const int rank = blockIdx.x & 1;
    const int n0 = (blockIdx.x >> 1) * BN;
    const int m0 = blockIdx.y * 2 * BM + rank * BM;   // this CTA's 128 A-rows
    const int nb = n0 + rank * BM;                    // this CTA's 128 B-rows

#if HAS_TCGEN05
    const uint32_t sb = smem_to_u32(smem);
    // mbarriers: full[s]    @ sb+64+8s  (leader-resident, count=2)
    //            done[s]    @ sb+128+8s (local, count=1, fed by mc commit)
    //            full_loc[s]@ sb+192+8s (local, count=256, fed by cp.async .noinc)
    if (tid == 0) {
#pragma unroll
        for (int s = 0; s < NSTG; s++) {
            MBARRIER_INIT(sb + 64 + 8 * s, 2);
            MBARRIER_INIT(sb + 128 + 8 * s, 1);
            MBARRIER_INIT(sb + 192 + 8 * s, 256);
        }
    }
    if (wid == 0) TCGEN05_ALLOC_CG2(sb + 0, 256);
    __syncthreads();
    uint32_t tmem;
    asm volatile("ld.shared.b32 %0, [%1];" : "=r"(tmem) : "r"(sb + 0));
    CLUSTER_SYNC();   // peer mbarriers live before any cluster arrive / MMA

    // per-thread cp.async mapping: 4 chunks of 16B per 128x64 sub-tile
    int swz[4]; size_t ga[4], gb[4];
#pragma unroll
    for (int j = 0; j < 4; j++) {
        int ch = tid + 256 * j;
        int row = ch >> 3, c16 = ch & 7;
        swz[j] = SWZ128(row * 128 + c16 * 16);
        ga[j] = (size_t)(m0 + row) * K + c16 * 8;
        gb[j] = (size_t)(nb + row) * K + c16 * 8;
    }

    int dph[NSTG]  = {0, 0, 0};   // done phases (all threads)
    int flph[NSTG] = {0, 0, 0};   // full_loc phases (warp0)
    int fph[NSTG]  = {0, 0, 0};   // leader full phases (rank0 warp0)
    const int ktiles = K / BKB;
    for (int t = 0; t < ktiles; t++) {
        const int buf = t % NSTG;
        if (t >= NSTG) {            // buffer reuse gate: prior MMA on buf done
            MBARRIER_WAIT_PARITY(sb + 128 + 8 * buf, dph[buf]);
            dph[buf] ^= 1;
        }
        const int k0 = t * BKB;
        const uint32_t st = sb + SM_HDR + buf * STAGE_BY;
#pragma unroll
        for (int j = 0; j < 4; j++) CP_ASYNC16(st + swz[j],           Ahi + ga[j] + k0);
#pragma unroll
        for (int j = 0; j < 4; j++) CP_ASYNC16(st + SUB + swz[j],     Alo + ga[j] + k0);
#pragma unroll
        for (int j = 0; j < 4; j++) CP_ASYNC16(st + 2 * SUB + swz[j], Bhi + gb[j] + k0);
#pragma unroll
        for (int j = 0; j < 4; j++) CP_ASYNC16(st + 3 * SUB + swz[j], Blo + gb[j] + k0);
        CP_ASYNC_MBAR_ARRIVE_NOINC(sb + 192 + 8 * buf);   // arrive on landing

        if (wid == 0) {
            // consumer chain (producers above never block on data)
            MBARRIER_WAIT_PARITY(sb + 192 + 8 * buf, flph[buf]);
            flph[buf] ^= 1;
            if (lid == 0) MBAR_ARRIVE_LEADER(sb + 64 + 8 * buf);
            if (rank == 0) {
                MBARRIER_WAIT_PARITY(sb + 64 + 8 * buf, fph[buf]);
                fph[buf] ^= 1;
                FENCE_PROXY_ASYNC();
                if (elect_one_pred()) {
                    u64 dAh = MAKE_DESC(st);
                    u64 dAl = MAKE_DESC(st + SUB);
                    u64 dBh = MAKE_DESC(st + 2 * SUB);
                    u64 dBl = MAKE_DESC(st + 3 * SUB);
#pragma unroll
                    for (int ks = 0; ks < 4; ks++) {
                        mma_f16_ss_cg2(tmem, dAh + 2 * ks, dBh + 2 * ks, !(t == 0 && ks == 0));
                        mma_f16_ss_cg2(tmem, dAh + 2 * ks, dBl + 2 * ks, 1u);
                        mma_f16_ss_cg2(tmem, dAl + 2 * ks, dBh + 2 * ks, 1u);
                    }
                    TCGEN05_COMMIT_MC_CG2(sb + 128 + 8 * buf, 3);
                }
            }
        }
    }

    // drain: last NSTG commits are still pending
    for (int i = ktiles - NSTG; i < ktiles; i++) {
        const int b = i % NSTG;
        MBARRIER_WAIT_PARITY(sb + 128 + 8 * b, dph[b]);
        dph[b] ^= 1;
    }
    TCGEN05_FENCE_AFTER();

    // epilogue: this CTA's TMEM holds its 128 rows x 256 cols of D
    if (wid < 4) {
        const int m = m0 + wid * 32 + lid;
#pragma unroll 1
        for (int chk = 0; chk < 8; chk++) {
            uint32_t dreg[32];
            TCGEN05_LD_X32(dreg, tmem + chk * 32);
            TCGEN05_WAIT_LD();
            size_t off = (size_t)m * Nn + n0 + chk * 32;
            float v[32];
#pragma unroll
            for (int i = 0; i < 32; i++) v[i] = __uint_as_float(dreg[i]);
            if (D) {
#pragma unroll
                for (int q = 0; q < 8; q++) {
                    float4 d = *(const float4*)(D + off + 4 * q);
                    v[4 * q + 0] += beta * d.x; v[4 * q + 1] += beta * d.y;
                    v[4 * q + 2] += beta * d.z; v[4 * q + 3] += beta * d.w;
                }
            }
#pragma unroll
            for (int q = 0; q < 8; q++)
                *(float4*)(C + off + 4 * q) =
                    make_float4(v[4 * q], v[4 * q + 1], v[4 * q + 2], v[4 * q + 3]);
            if (Chi) {
#pragma unroll
                for (int p = 0; p < 16; p++) {
                    __nv_bfloat16 h0, l0, h1, l1;
                    split2(v[2 * p], h0, l0); split2(v[2 * p + 1], h1, l1);
                    ((__nv_bfloat162*)(Chi + off))[p] = __nv_bfloat162(h0, h1);
                    ((__nv_bfloat162*)(Clo + off))[p] = __nv_bfloat162(l0, l1);
                }
            }
        }
        TCGEN05_FENCE_BEFORE();
    }

    __syncthreads();
    if (tid == 0) {
#pragma unroll
        for (int s = 0; s < NSTG; s++) {
            MBARRIER_INVAL(sb + 64 + 8 * s);
            MBARRIER_INVAL(sb + 128 + 8 * s);
            MBARRIER_INVAL(sb + 192 + 8 * s);
        }
    }
    __syncthreads();
    if (wid == 0) { TCGEN05_RELINQ_CG2(); TCGEN05_DEALLOC_CG2(tmem, 256); }
    CLUSTER_SYNC();   // no CTA exits while peer MMA/SMEM traffic may be live

#else
    // ============== SIMT fallback (base sm_103 target; never runs on GB300) ==
    float* As = (float*)smem;                    // [16][128]  As[k][m]
    float* Bs = (float*)(smem + 16 * 128 * 4);   // [16][128]  Bs[k][n]
    const int tm = (wid & 3) * 32 + (lid >> 3) * 8;
    const int tn_ = (wid >> 2) * 64 + (lid & 7) * 8;
    const int trow = tid >> 1;
    const int tk8  = (tid & 1) * 8;

    for (int h = 0; h < 2; h++) {
        const int n0h = n0 + 128 * h;
        float acc[8][8];
#pragma unroll
        for (int i = 0; i < 8; i++)
#pragma unroll
            for (int j = 0; j < 8; j++) acc[i][j] = 0.f;
        for (int k0 = 0; k0 < K; k0 += 16) {
            {
                size_t base = (size_t)(m0 + trow) * K + k0 + tk8;
                uint4 hh = *(const uint4*)(Ahi + base);
                uint4 ll = *(const uint4*)(Alo + base);
                const __nv_bfloat16* hp = (const __nv_bfloat16*)&hh;
                const __nv_bfloat16* lp = (const __nv_bfloat16*)&ll;
#pragma unroll
                for (int j = 0; j < 8; j++)
                    As[(tk8 + j) * 128 + trow] = __bfloat162float(hp[j]) + __bfloat162float(lp[j]);
            }
            {
                size_t base = (size_t)(n0h + trow) * K + k0 + tk8;
                uint4 hh = *(const uint4*)(Bhi + base);
                uint4 ll = *(const uint4*)(Blo + base);
                const __nv_bfloat16* hp = (const __nv_bfloat16*)&hh;
                const __nv_bfloat16* lp = (const __nv_bfloat16*)&ll;
#pragma unroll
                for (int j = 0; j < 8; j++)
                    Bs[(tk8 + j) * 128 + trow] = __bfloat162float(hp[j]) + __bfloat162float(lp[j]);
            }
            __syncthreads();
#pragma unroll
            for (int kk = 0; kk < 16; kk++) {
                float a[8], b[8];
#pragma unroll
                for (int i = 0; i < 8; i++) a[i] = As[kk * 128 + tm + i];
#pragma unroll
                for (int j = 0; j < 8; j++) b[j] = Bs[kk * 128 + tn_ + j];
#pragma unroll
                for (int i = 0; i < 8; i++)
#pragma unroll
                    for (int j = 0; j < 8; j++) acc[i][j] += a[i] * b[j];
            }
            __syncthreads();
        }
#pragma unroll
        for (int i = 0; i < 8; i++) {
            size_t off = (size_t)(m0 + tm + i) * Nn + n0h + tn_;
            float v[8];
#pragma unroll
            for (int j = 0; j < 8; j++) v[j] = acc[i][j];
            if (D) {
#pragma unroll
                for (int j = 0; j < 8; j++) v[j] += beta * D[off + j];
            }
#pragma unroll
            for (int j = 0; j < 8; j++) C[off + j] = v[j];
            if (Chi) {
#pragma unroll
                for (int p = 0; p < 4; p++) {
                    __nv_bfloat16 h0, l0, h1, l1;
                    split2(v[2 * p], h0, l0); split2(v[2 * p + 1], h1, l1);
                    ((__nv_bfloat162*)(Chi + off))[p] = __nv_bfloat162(h0, h1);
                    ((__nv_bfloat162*)(Clo + off))[p] = __nv_bfloat162(l0, l1);
                }
            }
        }
        __syncthreads();
    }
#endif
}

// ---------------- launch -----------------------------------------------------
extern "C" void kernel_launch(void* const* d_in, const int* in_sizes, int n_in,
                              void* d_out, int out_size) {
    const float* X  = (const float*)d_in[0];   // [8192, 2048]
    const float* Sf = (const float*)d_in[1];
    float* Y = (float*)d_out;

    cudaFuncSetAttribute(gemm_bf3, cudaFuncAttributeMaxDynamicSharedMemorySize, GEMM_SMEM);

    float *S, *S2, *S3, *T, *F, *Wf;
    cudaGetSymbolAddress((void**)&S, g_S);   cudaGetSymbolAddress((void**)&S2, g_S2);
    cudaGetSymbolAddress((void**)&S3, g_S3); cudaGetSymbolAddress((void**)&T, g_T);
    cudaGetSymbolAddress((void**)&F, g_F);   cudaGetSymbolAddress((void**)&Wf, g_Wf);
    __nv_bfloat16 *sAh, *sAl, *sBh, *sBl, *s2h, *s2l, *s3h, *s3l;
    __nv_bfloat16 *w2h, *w2l, *fh, *fl, *fth, *ftl, *wfh, *wfl, *xh, *xl;
    cudaGetSymbolAddress((void**)&sAh, g_sA_hi);  cudaGetSymbolAddress((void**)&sAl, g_sA_lo);
    cudaGetSymbolAddress((void**)&sBh, g_sB_hi);  cudaGetSymbolAddress((void**)&sBl, g_sB_lo);
    cudaGetSymbolAddress((void**)&s2h, g_s2_hi);  cudaGetSymbolAddress((void**)&s2l, g_s2_lo);
    cudaGetSymbolAddress((void**)&s3h, g_s3_hi);  cudaGetSymbolAddress((void**)&s3l, g_s3_lo);
    cudaGetSymbolAddress((void**)&w2h, g_w2t_hi); cudaGetSymbolAddress((void**)&w2l, g_w2t_lo);
    cudaGetSymbolAddress((void**)&fh, g_f_hi);    cudaGetSymbolAddress((void**)&fl, g_f_lo);
    cudaGetSymbolAddress((void**)&fth, g_ft_hi);  cudaGetSymbolAddress((void**)&ftl, g_ft_lo);
    cudaGetSymbolAddress((void**)&wfh, g_wft_hi); cudaGetSymbolAddress((void**)&wfl, g_wft_lo);
    cudaGetSymbolAddress((void**)&xh, g_x_hi);    cudaGetSymbolAddress((void**)&xl, g_x_lo);

    const int EW_BLOCKS = NSQ / 256;
    build_S_kernel<<<EW_BLOCKS, 256>>>(S, Sf, sAh, sAl, sBh, sBl);

    // grid.x = 2 * n_blocks (cluster pairs along x); grid.y = M / 256
    dim3 gSq(2 * (ND / BN), ND / 256);   // (16, 8)
    // S2 = S @ S
    gemm_bf3<<<gSq, 256, GEMM_SMEM>>>(S2, sAh, sAl, sBh, sBl, nullptr, 0.f, s2h, s2l, ND, ND, ND);
    // S3 = S2 @ S
    gemm_bf3<<<gSq, 256, GEMM_SMEM>>>(S3, s2h, s2l, sBh, sBl, nullptr, 0.f, s3h, s3l, ND, ND, ND);
    // W2^T (bf16) and T = Finit
    ew_prep_kernel<<<EW_BLOCKS, 256>>>(w2h, w2l, T, S, S2, S3);
    // F = S3 @ W2 + T
    gemm_bf3<<<gSq, 256, GEMM_SMEM>>>(F, s3h, s3l, w2h, w2l, T, 1.f, fh, fl, ND, ND, ND);
    // F^T bf16
    dim3 gT(ND / 32, ND / 32), bT(32, 8);
    transpose_conv<<<gT, bT>>>(F, fth, ftl, 0.f);
    // Wf = F @ F + 2F
    gemm_bf3<<<gSq, 256, GEMM_SMEM>>>(Wf, fh, fl, fth, ftl, F, 2.f, nullptr, nullptr, ND, ND, ND);
    // (Wf + I)^T bf16  (identity folded in -> big GEMM needs no D term)
    transpose_conv<<<gT, bT>>>(Wf, wfh, wfl, 1.f);
    // X -> hi/lo bf16
    conv_rm<<<(NB * ND / 4) / 256, 256>>>(X, xh, xl);
    // Y = X @ (Wf + I)
    dim3 gX(2 * (ND / BN), NB / 256);    // (16, 32)
    gemm_bf3<<<gX, 256, GEMM_SMEM>>>(Y, xh, xl, wfh, wfl, nullptr, 0.f, nullptr, nullptr, NB, ND, ND);
}

// round 13
// speedup vs baseline: 1.0182x; 1.0182x over previous
#include <cuda_runtime.h>
#include <cuda_bf16.h>
#include <cstdint>

typedef unsigned long long u64;

#define ND 2048
#define NB 8192
#define NSQ (ND*ND)

// tcgen05 is arch-SPECIFIC (sm_103a pass only); base compute_103 pass gets a
// SIMT fallback body so ptxas never sees tcgen05 on the base target.
#if defined(__CUDA_ARCH__) && (defined(__CUDA_ARCH_FEAT_SM103_ALL) || defined(__CUDA_ARCH_FEAT_SM100_ALL) || defined(__CUDA_ARCH_FEAT_SM101_ALL))
#define HAS_TCGEN05 1
#else
#define HAS_TCGEN05 0
#endif

// ---------------- scratch (__device__ globals; allocation-free rule) --------
__device__ float g_S [NSQ];
__device__ float g_S2[NSQ];
__device__ float g_S3[NSQ];
__device__ float g_T [NSQ];
__device__ float g_F [NSQ];
__device__ float g_Wf[NSQ];

__device__ __nv_bfloat16 g_sA_hi[NSQ],  g_sA_lo[NSQ];    // S   (A-side)
__device__ __nv_bfloat16 g_sB_hi[NSQ],  g_sB_lo[NSQ];    // S^T = -S (B-side)
__device__ __nv_bfloat16 g_s2_hi[NSQ],  g_s2_lo[NSQ];    // S2  (A-side)
__device__ __nv_bfloat16 g_s3_hi[NSQ],  g_s3_lo[NSQ];    // S3  (A-side)
__device__ __nv_bfloat16 g_w2t_hi[NSQ], g_w2t_lo[NSQ];   // W2^T (B-side)
__device__ __nv_bfloat16 g_f_hi[NSQ],   g_f_lo[NSQ];     // F   (A-side)
__device__ __nv_bfloat16 g_ft_hi[NSQ],  g_ft_lo[NSQ];    // F^T (B-side)
__device__ __nv_bfloat16 g_wft_hi[NSQ], g_wft_lo[NSQ];   // (Wf+I)^T (B-side)
__device__ __nv_bfloat16 g_x_hi[NB*ND], g_x_lo[NB*ND];   // X   (A-side)

// ---------------- common helpers --------------------------------------------
__device__ __forceinline__ void split2(float v, __nv_bfloat16& h, __nv_bfloat16& l) {
    h = __float2bfloat16(v);
    l = __float2bfloat16(v - __bfloat162float(h));
}

#define SWZ128(x) ((x) ^ (((x) >> 3) & 0x70))

#if HAS_TCGEN05
__device__ __forceinline__ uint32_t smem_to_u32(const void* p) {
    uint32_t a;
    asm("{ .reg .u64 t; cvta.to.shared.u64 t, %1; cvt.u32.u64 %0, t; }" : "=r"(a) : "l"(p));
    return a;
}
__device__ __forceinline__ uint32_t elect_one_pred() {
    uint32_t p;
    asm volatile("{\n\t.reg .pred p;\n\telect.sync _|p, 0xFFFFFFFF;\n\t"
                 "selp.b32 %0, 1, 0, p;\n\t}" : "=r"(p));
    return p;
}
#define MBARRIER_INIT(addr, cnt) \
    asm volatile("mbarrier.init.shared.b64 [%0], %1;" :: "r"((uint32_t)(addr)), "r"((uint32_t)(cnt)) : "memory")
#define MBARRIER_INVAL(addr) \
    asm volatile("mbarrier.inval.shared.b64 [%0];" :: "r"((uint32_t)(addr)) : "memory")
#define MBARRIER_WAIT_PARITY(mbar, par) do {                                       \
    uint32_t _m = (uint32_t)(mbar); uint32_t _p = (uint32_t)(par); uint32_t _d;    \
    asm volatile("{\n\t.reg .pred p;\n\t"                                          \
        "mbarrier.try_wait.parity.acquire.cta.shared::cta.b64 p, [%1], %2;\n\t"    \
        "selp.b32 %0, 1, 0, p;\n\t}" : "=r"(_d) : "r"(_m), "r"(_p) : "memory");    \
    if (!_d) {                                                                     \
        asm volatile("{\n\t.reg .pred P1;\n\t"                                     \
        "WL_%=:\n\t"                                                               \
        "mbarrier.try_wait.parity.acquire.cta.shared::cta.b64 P1, [%0], %1, 0x989680;\n\t" \
        "@P1 bra.uni WD_%=;\n\t"                                                   \
        "bra.uni WL_%=;\n\t"                                                       \
        "WD_%=:\n\t}" :: "r"(_m), "r"(_p) : "memory");                             \
    }                                                                              \
} while (0)
// arrive on the same-offset mbarrier in cluster rank 0 (leader)
#define MBAR_ARRIVE_LEADER(localaddr) \
    asm volatile("{\n\t.reg .b32 ra;\n\t" \
        "mapa.shared::cluster.u32 ra, %0, 0;\n\t" \
        "mbarrier.arrive.shared::cluster.b64 _, [ra];\n\t}" \
        :: "r"((uint32_t)(localaddr)) : "memory")
#define CLUSTER_SYNC() do { \
    asm volatile("barrier.cluster.arrive.aligned;" ::: "memory"); \
    asm volatile("barrier.cluster.wait.aligned;" ::: "memory"); \
} while (0)
#define TCGEN05_ALLOC_CG2(sm, n) \
    asm volatile("tcgen05.alloc.cta_group::2.sync.aligned.shared::cta.b32 [%0], %1;" \
                 :: "r"((uint32_t)(sm)), "r"((uint32_t)(n)) : "memory")
#define TCGEN05_DEALLOC_CG2(t, n) \
    asm volatile("tcgen05.dealloc.cta_group::2.sync.aligned.b32 %0, %1;" :: "r"(t), "r"((uint32_t)(n)))
#define TCGEN05_RELINQ_CG2() \
    asm volatile("tcgen05.relinquish_alloc_permit.cta_group::2.sync.aligned;")
#define TCGEN05_COMMIT_MC_CG2(mbar, mask) \
    asm volatile("tcgen05.commit.cta_group::2.mbarrier::arrive::one.shared::cluster.multicast::cluster.b64 [%0], %1;" \
                 :: "r"((uint32_t)(mbar)), "h"((uint16_t)(mask)) : "memory")
#define TCGEN05_FENCE_AFTER()  asm volatile("tcgen05.fence::after_thread_sync;" ::: "memory")
#define TCGEN05_FENCE_BEFORE() asm volatile("tcgen05.fence::before_thread_sync;" ::: "memory")
#define TCGEN05_WAIT_LD()      asm volatile("tcgen05.wait::ld.sync.aligned;" ::: "memory")
#define FENCE_PROXY_ASYNC()    asm volatile("fence.proxy.async;" ::: "memory")
#define CP_ASYNC16(dst, src) \
    asm volatile("cp.async.cg.shared.global [%0], [%1], 16;" :: "r"((uint32_t)(dst)), "l"(src) : "memory")
// arrive-on-completion WITHOUT incrementing the pending count (.noinc):
// barrier init count pre-arms one arrive per producer thread.
#define CP_ASYNC_MBAR_ARRIVE_NOINC(m) \
    asm volatile("cp.async.mbarrier.arrive.noinc.shared::cta.b64 [%0];" :: "r"((uint32_t)(m)) : "memory")

#define TCGEN05_LD_X32(r, addr) \
    asm volatile("tcgen05.ld.sync.aligned.32x32b.x32.b32 " \
        "{%0, %1, %2, %3, %4, %5, %6, %7, %8, %9, %10, %11, %12, %13, %14, %15, " \
        " %16, %17, %18, %19, %20, %21, %22, %23, %24, %25, %26, %27, %28, %29, %30, %31}, [%32];" \
        : "=r"((r)[0]),  "=r"((r)[1]),  "=r"((r)[2]),  "=r"((r)[3]),  \
          "=r"((r)[4]),  "=r"((r)[5]),  "=r"((r)[6]),  "=r"((r)[7]),  \
          "=r"((r)[8]),  "=r"((r)[9]),  "=r"((r)[10]), "=r"((r)[11]), \
          "=r"((r)[12]), "=r"((r)[13]), "=r"((r)[14]), "=r"((r)[15]), \
          "=r"((r)[16]), "=r"((r)[17]), "=r"((r)[18]), "=r"((r)[19]), \
          "=r"((r)[20]), "=r"((r)[21]), "=r"((r)[22]), "=r"((r)[23]), \
          "=r"((r)[24]), "=r"((r)[25]), "=r"((r)[26]), "=r"((r)[27]), \
          "=r"((r)[28]), "=r"((r)[29]), "=r"((r)[30]), "=r"((r)[31]) \
        : "r"(addr))

// SW128 K-major smem descriptor (layout=2, version=1, SBO=64, LBO=1)
static constexpr u64 DESC_BASE_SW128 =
    (u64(2) << 61) | (u64(1) << 46) | (u64(64) << 32) | (u64(1) << 16);
#define MAKE_DESC(a) (DESC_BASE_SW128 | ((u64)((a) >> 4) & 0x3FFF))

// cg2 bf16 SS MMA: idesc = F32 | BF16 a | BF16 b | (N/8)<<17 | (M/16)<<24
#define MMA_IDESC_CG2 0x10400490u   // M=256 (pair), N=256
__device__ __forceinline__ void mma_f16_ss_cg2(uint32_t d, u64 a, u64 b, uint32_t en) {
    asm volatile("{\n\t.reg .pred p;\n\tsetp.ne.u32 p, %4, 0;\n\t"
        "tcgen05.mma.cta_group::2.kind::f16 [%0], %1, %2, %3, "
        "{%5, %5, %5, %5, %5, %5, %5, %5}, p;\n\t}"
        :: "r"(d), "l"(a), "l"(b), "r"(MMA_IDESC_CG2), "r"(en), "r"(0u) : "memory");
}
#endif  // HAS_TCGEN05

// ---------------- elementwise kernels ---------------------------------------
__global__ void build_S_kernel(float* __restrict__ S, const float* __restrict__ Sf,
                               __nv_bfloat16* __restrict__ ahi, __nv_bfloat16* __restrict__ alo,
                               __nv_bfloat16* __restrict__ bhi, __nv_bfloat16* __restrict__ blo) {
    int idx = blockIdx.x * blockDim.x + threadIdx.x;
    int r = idx >> 11, c = idx & (ND - 1);
    float v = 0.f;
    if (r != c) {
        int rr = r < c ? r : c, cc = r < c ? c : r;
        int f = rr * (2 * ND - rr - 1) / 2 + (cc - rr - 1);
        v = Sf[f];
        if (r > c) v = -v;
    }
    S[idx] = v;
    __nv_bfloat16 h, l;
    split2(v, h, l);  ahi[idx] = h; alo[idx] = l;
    split2(-v, h, l); bhi[idx] = h; blo[idx] = l;   // S^T = -S
}

// W2^T = I/48 - S/384 + S2/3840 - S3/46080 (bf16 split);  T = S2/8 + S/2 (fp32)
__global__ void ew_prep_kernel(__nv_bfloat16* __restrict__ w2hi, __nv_bfloat16* __restrict__ w2lo,
                               float* __restrict__ T,
                               const float* __restrict__ S, const float* __restrict__ S2,
                               const float* __restrict__ S3) {
    int idx = blockIdx.x * blockDim.x + threadIdx.x;
    int r = idx >> 11, c = idx & (ND - 1);
    float s = S[idx], s2 = S2[idx], s3 = S3[idx];
    float w2t = -s3 * (1.f / 46080.f) + s2 * (1.f / 3840.f) - s * (1.f / 384.f);
    if (r == c) w2t += (1.f / 48.f);
    __nv_bfloat16 h, l;
    split2(w2t, h, l); w2hi[idx] = h; w2lo[idx] = l;
    T[idx] = s2 * 0.125f + s * 0.5f;
}

// 32x32 tiled transpose + optional diagonal add + bf16 split
__global__ void transpose_conv(const float* __restrict__ in,
                               __nv_bfloat16* __restrict__ thi, __nv_bfloat16* __restrict__ tlo,
                               float idadd) {
    __shared__ float tile[32][33];
    int bx = blockIdx.x * 32, by = blockIdx.y * 32;
    int tx = threadIdx.x, ty = threadIdx.y;   // 32 x 8
#pragma unroll
    for (int j = 0; j < 4; j++)
        tile[ty + 8 * j][tx] = in[(size_t)(by + ty + 8 * j) * ND + bx + tx];
    __syncthreads();
#pragma unroll
    for (int j = 0; j < 4; j++) {
        int ro = bx + ty + 8 * j, co = by + tx;
        float v = tile[tx][ty + 8 * j];
        if (ro == co) v += idadd;
        __nv_bfloat16 h, l; split2(v, h, l);
        size_t o = (size_t)ro * ND + co;
        thi[o] = h; tlo[o] = l;
    }
}

// row-major fp32 -> hi/lo bf16 (for X)
__global__ void conv_rm(const float* __restrict__ in,
                        __nv_bfloat16* __restrict__ hi, __nv_bfloat16* __restrict__ lo) {
    int i = blockIdx.x * blockDim.x + threadIdx.x;
    float4 v = ((const float4*)in)[i];
    __nv_bfloat16 h0, l0, h1, l1, h2, l2, h3, l3;
    split2(v.x, h0, l0); split2(v.y, h1, l1); split2(v.z, h2, l2); split2(v.w, h3, l3);
    ((__nv_bfloat162*)hi)[2 * i]     = __nv_bfloat162(h0, h1);
    ((__nv_bfloat162*)hi)[2 * i + 1] = __nv_bfloat162(h2, h3);
    ((__nv_bfloat162*)lo)[2 * i]     = __nv_bfloat162(l0, l1);
    ((__nv_bfloat162*)lo)[2 * i + 1] = __nv_bfloat162(l2, l3);
}

// ---------------- GEMM: C = A @ B^T, 2-CTA cluster computes 256x256 tile ----
// Warp-specialized async pipeline (288 threads):
//   warps 1-8 (256 threads): pure producers. Gate on done[buf] only; issue
//     cp.async + .noinc arrive onto full_loc[buf] (count=256); run 3 ahead.
//   warp 0: pure consumer. wait full_loc -> arrive leader full (count=2) ->
//     rank0 waits full -> fence -> 12 cg2 MMA dispatches -> mc commit -> done.
// Warp0 never produces, so its blocking no longer serializes load latency
// into the stage period (the R11 flaw). Steady state = max(transfer, MMA).
#define BM 128          // per-CTA M share (pair = 256)
#define BN 256
#define BKB 64
#define SUB 16384                         // one 128x64 bf16 sub-tile
#define STAGE_BY (4 * SUB)                // Ahi,Alo,Bhi,Blo = 64 KB
#define NSTG 3
#define SM_HDR 1024
#define GEMM_SMEM (SM_HDR + NSTG * STAGE_BY)  // 197632 bytes
#define GTHREADS 288

__global__ void __launch_bounds__(GTHREADS, 1) __cluster_dims__(2, 1, 1)
gemm_bf3(float* __restrict__ C,
         const __nv_bfloat16* __restrict__ Ahi, const __nv_bfloat16* __restrict__ Alo,
         const __nv_bfloat16* __restrict__ Bhi, const __nv_bfloat16* __restrict__ Blo,
         const float* __restrict__ D, float beta,
         __nv_bfloat16* __restrict__ Chi, __nv_bfloat16* __restrict__ Clo,
         int M, int Nn, int K) {
    extern __shared__ char smem[];
    const int tid = threadIdx.x, wid = tid >> 5, lid = tid & 31;
    const int rank = blockIdx.x & 1;
    const int n0 = (blockIdx.x >> 1) * BN;
    const int m0 = blockIdx.y * 2 * BM + rank * BM;   // this CTA's 128 A-rows
    const int nb = n0 + rank * BM;                    // this CTA's 128 B-rows

#if HAS_TCGEN05
    const uint32_t sb = smem_to_u32(smem);
    // mbarriers: full[s]    @ sb+64+8s  (leader-resident, count=2)
    //            done[s]    @ sb+128+8s (local, count=1, fed by mc commit)
    //            full_loc[s]@ sb+192+8s (local, count=256, cp.async .noinc)
    if (tid == 0) {
#pragma unroll
        for (int s = 0; s < NSTG; s++) {
            MBARRIER_INIT(sb + 64 + 8 * s, 2);
            MBARRIER_INIT(sb + 128 + 8 * s, 1);
            MBARRIER_INIT(sb + 192 + 8 * s, 256);
        }
    }
    if (wid == 0) TCGEN05_ALLOC_CG2(sb + 0, 256);
    __syncthreads();
    uint32_t tmem;
    asm volatile("ld.shared.b32 %0, [%1];" : "=r"(tmem) : "r"(sb + 0));
    CLUSTER_SYNC();   // peer mbarriers live before any cluster arrive / MMA

    // producer thread id (warps 1-8): 4 chunks of 16B per 128x64 sub-tile
    const int ptid = (tid >= 32) ? (tid - 32) : 0;
    int swz[4]; size_t ga[4], gb[4];
#pragma unroll
    for (int j = 0; j < 4; j++) {
        int ch = ptid + 256 * j;
        int row = ch >> 3, c16 = ch & 7;
        swz[j] = SWZ128(row * 128 + c16 * 16);
        ga[j] = (size_t)(m0 + row) * K + c16 * 8;
        gb[j] = (size_t)(nb + row) * K + c16 * 8;
    }

    int dph[NSTG]  = {0, 0, 0};   // done phases (producers)
    int flph[NSTG] = {0, 0, 0};   // full_loc phases (warp0)
    int fph[NSTG]  = {0, 0, 0};   // leader full phases (rank0 warp0)
    const int ktiles = K / BKB;
    for (int t = 0; t < ktiles; t++) {
        const int buf = t % NSTG;
        const uint32_t st = sb + SM_HDR + buf * STAGE_BY;
        if (tid >= 32) {
            // ---- producer: gate on buffer-free only; never touch data waits
            if (t >= NSTG) {
                MBARRIER_WAIT_PARITY(sb + 128 + 8 * buf, dph[buf]);
                dph[buf] ^= 1;
            }
            const int k0 = t * BKB;
#pragma unroll
            for (int j = 0; j < 4; j++) CP_ASYNC16(st + swz[j],           Ahi + ga[j] + k0);
#pragma unroll
            for (int j = 0; j < 4; j++) CP_ASYNC16(st + SUB + swz[j],     Alo + ga[j] + k0);
#pragma unroll
            for (int j = 0; j < 4; j++) CP_ASYNC16(st + 2 * SUB + swz[j], Bhi + gb[j] + k0);
#pragma unroll
            for (int j = 0; j < 4; j++) CP_ASYNC16(st + 3 * SUB + swz[j], Blo + gb[j] + k0);
            CP_ASYNC_MBAR_ARRIVE_NOINC(sb + 192 + 8 * buf);
        } else {
            // ---- consumer (warp 0): chain per stage, MMAs queue async
            MBARRIER_WAIT_PARITY(sb + 192 + 8 * buf, flph[buf]);
            flph[buf] ^= 1;
            if (lid == 0) MBAR_ARRIVE_LEADER(sb + 64 + 8 * buf);
            if (rank == 0) {
                MBARRIER_WAIT_PARITY(sb + 64 + 8 * buf, fph[buf]);
                fph[buf] ^= 1;
                FENCE_PROXY_ASYNC();
                if (elect_one_pred()) {
                    u64 dAh = MAKE_DESC(st);
                    u64 dAl = MAKE_DESC(st + SUB);
                    u64 dBh = MAKE_DESC(st + 2 * SUB);
                    u64 dBl = MAKE_DESC(st + 3 * SUB);
#pragma unroll
                    for (int ks = 0; ks < 4; ks++) {
                        mma_f16_ss_cg2(tmem, dAh + 2 * ks, dBh + 2 * ks, !(t == 0 && ks == 0));
                        mma_f16_ss_cg2(tmem, dAh + 2 * ks, dBl + 2 * ks, 1u);
                        mma_f16_ss_cg2(tmem, dAl + 2 * ks, dBh + 2 * ks, 1u);
                    }
                    TCGEN05_COMMIT_MC_CG2(sb + 128 + 8 * buf, 3);
                }
            }
        }
    }

    // drain: producers (who tracked done phases) absorb the last NSTG commits,
    // then a block barrier publishes completion to warp 0.
    if (tid >= 32) {
        for (int i = ktiles - NSTG; i < ktiles; i++) {
            const int b = i % NSTG;
            MBARRIER_WAIT_PARITY(sb + 128 + 8 * b, dph[b]);
            dph[b] ^= 1;
        }
    }
    __syncthreads();
    TCGEN05_FENCE_AFTER();

    // epilogue: this CTA's TMEM holds its 128 rows x 256 cols of D
    if (wid < 4) {
        const int m = m0 + wid * 32 + lid;
#pragma unroll 1
        for (int chk = 0; chk < 8; chk++) {
            uint32_t dreg[32];
            TCGEN05_LD_X32(dreg, tmem + chk * 32);
            TCGEN05_WAIT_LD();
            size_t off = (size_t)m * Nn + n0 + chk * 32;
            float v[32];
#pragma unroll
            for (int i = 0; i < 32; i++) v[i] = __uint_as_float(dreg[i]);
            if (D) {
#pragma unroll
                for (int q = 0; q < 8; q++) {
                    float4 d = *(const float4*)(D + off + 4 * q);
                    v[4 * q + 0] += beta * d.x; v[4 * q + 1] += beta * d.y;
                    v[4 * q + 2] += beta * d.z; v[4 * q + 3] += beta * d.w;
                }
            }
#pragma unroll
            for (int q = 0; q < 8; q++)
                *(float4*)(C + off + 4 * q) =
                    make_float4(v[4 * q], v[4 * q + 1], v[4 * q + 2], v[4 * q + 3]);
            if (Chi) {
#pragma unroll
                for (int p = 0; p < 16; p++) {
                    __nv_bfloat16 h0, l0, h1, l1;
                    split2(v[2 * p], h0, l0); split2(v[2 * p + 1], h1, l1);
                    ((__nv_bfloat162*)(Chi + off))[p] = __nv_bfloat162(h0, h1);
                    ((__nv_bfloat162*)(Clo + off))[p] = __nv_bfloat162(l0, l1);
                }
            }
        }
        TCGEN05_FENCE_BEFORE();
    }

    __syncthreads();
    if (tid == 0) {
#pragma unroll
        for (int s = 0; s < NSTG; s++) {
            MBARRIER_INVAL(sb + 64 + 8 * s);
            MBARRIER_INVAL(sb + 128 + 8 * s);
            MBARRIER_INVAL(sb + 192 + 8 * s);
        }
    }
    __syncthreads();
    if (wid == 0) { TCGEN05_RELINQ_CG2(); TCGEN05_DEALLOC_CG2(tmem, 256); }
    CLUSTER_SYNC();   // no CTA exits while peer MMA/SMEM traffic may be live

#else
    // ============== SIMT fallback (base sm_103 target; never runs on GB300) ==
    float* As = (float*)smem;                    // [16][128]  As[k][m]
    float* Bs = (float*)(smem + 16 * 128 * 4);   // [16][128]  Bs[k][n]
    const int tm = (wid & 3) * 32 + (lid >> 3) * 8;
    const int tn_ = (wid >> 2) * 64 + (lid & 7) * 8;
    const int trow = tid >> 1;
    const int tk8  = (tid & 1) * 8;
    const bool act = (tid < 256);

    for (int h = 0; h < 2; h++) {
        const int n0h = n0 + 128 * h;
        float acc[8][8];
#pragma unroll
        for (int i = 0; i < 8; i++)
#pragma unroll
            for (int j = 0; j < 8; j++) acc[i][j] = 0.f;
        for (int k0 = 0; k0 < K; k0 += 16) {
            if (act) {
                size_t base = (size_t)(m0 + trow) * K + k0 + tk8;
                uint4 hh = *(const uint4*)(Ahi + base);
                uint4 ll = *(const uint4*)(Alo + base);
                const __nv_bfloat16* hp = (const __nv_bfloat16*)&hh;
                const __nv_bfloat16* lp = (const __nv_bfloat16*)&ll;
#pragma unroll
                for (int j = 0; j < 8; j++)
                    As[(tk8 + j) * 128 + trow] = __bfloat162float(hp[j]) + __bfloat162float(lp[j]);
                size_t base2 = (size_t)(n0h + trow) * K + k0 + tk8;
                uint4 hh2 = *(const uint4*)(Bhi + base2);
                uint4 ll2 = *(const uint4*)(Blo + base2);
                const __nv_bfloat16* hp2 = (const __nv_bfloat16*)&hh2;
                const __nv_bfloat16* lp2 = (const __nv_bfloat16*)&ll2;
#pragma unroll
                for (int j = 0; j < 8; j++)
                    Bs[(tk8 + j) * 128 + trow] = __bfloat162float(hp2[j]) + __bfloat162float(lp2[j]);
            }
            __syncthreads();
            if (act) {
#pragma unroll
                for (int kk = 0; kk < 16; kk++) {
                    float a[8], b[8];
#pragma unroll
                    for (int i = 0; i < 8; i++) a[i] = As[kk * 128 + tm + i];
#pragma unroll
                    for (int j = 0; j < 8; j++) b[j] = Bs[kk * 128 + tn_ + j];
#pragma unroll
                    for (int i = 0; i < 8; i++)
#pragma unroll
                        for (int j = 0; j < 8; j++) acc[i][j] += a[i] * b[j];
                }
            }
            __syncthreads();
        }
        if (act) {
#pragma unroll
            for (int i = 0; i < 8; i++) {
                size_t off = (size_t)(m0 + tm + i) * Nn + n0h + tn_;
                float v[8];
#pragma unroll
                for (int j = 0; j < 8; j++) v[j] = acc[i][j];
                if (D) {
#pragma unroll
                    for (int j = 0; j < 8; j++) v[j] += beta * D[off + j];
                }
#pragma unroll
                for (int j = 0; j < 8; j++) C[off + j] = v[j];
                if (Chi) {
#pragma unroll
                    for (int p = 0; p < 4; p++) {
                        __nv_bfloat16 h0, l0, h1, l1;
                        split2(v[2 * p], h0, l0); split2(v[2 * p + 1], h1, l1);
                        ((__nv_bfloat162*)(Chi + off))[p] = __nv_bfloat162(h0, h1);
                        ((__nv_bfloat162*)(Clo + off))[p] = __nv_bfloat162(l0, l1);
                    }
                }
            }
        }
        __syncthreads();
    }
#endif
}

// ---------------- launch -----------------------------------------------------
extern "C" void kernel_launch(void* const* d_in, const int* in_sizes, int n_in,
                              void* d_out, int out_size) {
    const float* X  = (const float*)d_in[0];   // [8192, 2048]
    const float* Sf = (const float*)d_in[1];
    float* Y = (float*)d_out;

    cudaFuncSetAttribute(gemm_bf3, cudaFuncAttributeMaxDynamicSharedMemorySize, GEMM_SMEM);

    float *S, *S2, *S3, *T, *F, *Wf;
    cudaGetSymbolAddress((void**)&S, g_S);   cudaGetSymbolAddress((void**)&S2, g_S2);
    cudaGetSymbolAddress((void**)&S3, g_S3); cudaGetSymbolAddress((void**)&T, g_T);
    cudaGetSymbolAddress((void**)&F, g_F);   cudaGetSymbolAddress((void**)&Wf, g_Wf);
    __nv_bfloat16 *sAh, *sAl, *sBh, *sBl, *s2h, *s2l, *s3h, *s3l;
    __nv_bfloat16 *w2h, *w2l, *fh, *fl, *fth, *ftl, *wfh, *wfl, *xh, *xl;
    cudaGetSymbolAddress((void**)&sAh, g_sA_hi);  cudaGetSymbolAddress((void**)&sAl, g_sA_lo);
    cudaGetSymbolAddress((void**)&sBh, g_sB_hi);  cudaGetSymbolAddress((void**)&sBl, g_sB_lo);
    cudaGetSymbolAddress((void**)&s2h, g_s2_hi);  cudaGetSymbolAddress((void**)&s2l, g_s2_lo);
    cudaGetSymbolAddress((void**)&s3h, g_s3_hi);  cudaGetSymbolAddress((void**)&s3l, g_s3_lo);
    cudaGetSymbolAddress((void**)&w2h, g_w2t_hi); cudaGetSymbolAddress((void**)&w2l, g_w2t_lo);
    cudaGetSymbolAddress((void**)&fh, g_f_hi);    cudaGetSymbolAddress((void**)&fl, g_f_lo);
    cudaGetSymbolAddress((void**)&fth, g_ft_hi);  cudaGetSymbolAddress((void**)&ftl, g_ft_lo);
    cudaGetSymbolAddress((void**)&wfh, g_wft_hi); cudaGetSymbolAddress((void**)&wfl, g_wft_lo);
    cudaGetSymbolAddress((void**)&xh, g_x_hi);    cudaGetSymbolAddress((void**)&xl, g_x_lo);

    const int EW_BLOCKS = NSQ / 256;
    build_S_kernel<<<EW_BLOCKS, 256>>>(S, Sf, sAh, sAl, sBh, sBl);

    // grid.x = 2 * n_blocks (cluster pairs along x); grid.y = M / 256
    dim3 gSq(2 * (ND / BN), ND / 256);   // (16, 8)
    // S2 = S @ S
    gemm_bf3<<<gSq, GTHREADS, GEMM_SMEM>>>(S2, sAh, sAl, sBh, sBl, nullptr, 0.f, s2h, s2l, ND, ND, ND);
    // S3 = S2 @ S
    gemm_bf3<<<gSq, GTHREADS, GEMM_SMEM>>>(S3, s2h, s2l, sBh, sBl, nullptr, 0.f, s3h, s3l, ND, ND, ND);
    // W2^T (bf16) and T = Finit
    ew_prep_kernel<<<EW_BLOCKS, 256>>>(w2h, w2l, T, S, S2, S3);
    // F = S3 @ W2 + T
    gemm_bf3<<<gSq, GTHREADS, GEMM_SMEM>>>(F, s3h, s3l, w2h, w2l, T, 1.f, fh, fl, ND, ND, ND);
    // F^T bf16
    dim3 gT(ND / 32, ND / 32), bT(32, 8);
    transpose_conv<<<gT, bT>>>(F, fth, ftl, 0.f);
    // Wf = F @ F + 2F
    gemm_bf3<<<gSq, GTHREADS, GEMM_SMEM>>>(Wf, fh, fl, fth, ftl, F, 2.f, nullptr, nullptr, ND, ND, ND);
    // (Wf + I)^T bf16  (identity folded in -> big GEMM needs no D term)
    transpose_conv<<<gT, bT>>>(Wf, wfh, wfl, 1.f);
    // X -> hi/lo bf16
    conv_rm<<<(NB * ND / 4) / 256, 256>>>(X, xh, xl);
    // Y = X @ (Wf + I)
    dim3 gX(2 * (ND / BN), NB / 256);    // (16, 32)
    gemm_bf3<<<gX, GTHREADS, GEMM_SMEM>>>(Y, xh, xl, wfh, wfl, nullptr, 0.f, nullptr, nullptr, NB, ND, ND);
}